// round 17
// baseline (speedup 1.0000x reference)
#include <cuda_runtime.h>
#include <cstdint>

typedef unsigned int u32;
typedef unsigned long long u64;

#define BBATCH 2048
#define SSEQ 256
#define NTOK 6
#define STARTTOK 4
#define NT 256

#define RECONS_N (BBATCH*SSEQ*4)
#define TOKOFF RECONS_N
#define MUOFF (RECONS_N + BBATCH*SSEQ)
#define LVOFF (MUOFF + BBATCH*3)
#define FULLN (LVOFF + BBATCH*3)

// common SMEM float offsets
#define O_W1A 0        /* [d][u][4] = wir,whr,wiz,whz : 16384 */
#define O_W1B 16384    /* [d][u][2] = win,whn : 8192 */
#define O_W0A 24576    /* [d][u][4] = w0r,w0z,w0n,pad : 16384 */
#define O_TAB 40960    /* 6*192 */
#define O_B0  42112
#define O_BI1 42304
#define O_BH1 42496
#define O_H0B 42688    /* [2][64][20] : 2560 */
#define O_H1B 45248    /* [2][64][20] : 2560 */
#define O_XPR 47808    /* 8 u64-slots x 128 : 2048 floats */
#define O_XL0 49856    /* 12 u64-slots x 128 : 3072 floats */
#define O_CEND 52928
// encoder-only
#define O_MUW 52928
#define O_VARW 53120
#define O_MUB 53312
#define O_VARB 53316
#define O_PRJW 53320
#define O_PRJB 53512
#define O_ZS  53576
#define O_TOKS 53624   /* u8[4096] = 1024 floats */
#define ENC_F 54648
// decoder-only
#define O_HW  52928    /* 256 */
#define O_HB2 53184    /* 4 */
#define O_K0  53188    /* 256 */
#define O_K1  53444    /* 256 */
#define O_TOKD 53700   /* 16 ints */
#define O_LSTG 53716   /* 256 */
#define DEC_F 53972

__device__ float g_hz[BBATCH*64];

// ---------- f32x2 helpers ----------
__device__ __forceinline__ void upk2(u64 v, float& a, float& b){
    asm("mov.b64 {%0,%1},%2;" : "=f"(a), "=f"(b) : "l"(v));
}
__device__ __forceinline__ u64 pack2(float x, float y){
    u64 r; asm("mov.b64 %0,{%1,%2};" : "=l"(r) : "f"(x), "f"(y)); return r;
}
__device__ __forceinline__ u64 dupf(float f){ return pack2(f, f); }
__device__ __forceinline__ u64 ff2(u64 a, u64 b, u64 c){
    u64 d; asm("fma.rn.f32x2 %0,%1,%2,%3;" : "=l"(d) : "l"(a), "l"(b), "l"(c)); return d;
}
__device__ __forceinline__ u64 add2(u64 a, u64 b){
    u64 c; asm("add.rn.f32x2 %0,%1,%2;" : "=l"(c) : "l"(a), "l"(b)); return c;
}
__device__ __forceinline__ u64 d2u(double d){ return (u64)__double_as_longlong(d); }

// ---------- threefry2x32-20 (exact JAX) ----------
__device__ __forceinline__ void threefry(u32 k0, u32 k1, u32 x0, u32 x1, u32& o0, u32& o1){
    u32 ks2 = k0 ^ k1 ^ 0x1BD11BDAu;
    x0 += k0; x1 += k1;
#define TFR(r) { x0 += x1; x1 = __funnelshift_l(x1, x1, (r)); x1 ^= x0; }
    TFR(13) TFR(15) TFR(26) TFR(6)   x0 += k1;  x1 += ks2 + 1u;
    TFR(17) TFR(29) TFR(16) TFR(24)  x0 += ks2; x1 += k0 + 2u;
    TFR(13) TFR(15) TFR(26) TFR(6)   x0 += k0;  x1 += k1 + 3u;
    TFR(17) TFR(29) TFR(16) TFR(24)  x0 += k1;  x1 += ks2 + 4u;
    TFR(13) TFR(15) TFR(26) TFR(6)   x0 += ks2; x1 += k0 + 5u;
#undef TFR
    o0 = x0; o1 = x1;
}
__device__ __forceinline__ u32 tf_bits32(u32 k0, u32 k1, u32 i){
    u32 a, b; threefry(k0, k1, 0u, i, a, b); return a ^ b;
}
__device__ __forceinline__ float bits2f(u32 b){
    return __uint_as_float((b >> 9) | 0x3f800000u) - 1.0f;
}
__device__ __forceinline__ float sigf(float x){ return 0.5f + 0.5f * tanhf(0.5f * x); }

__device__ __forceinline__ float erfinv_f(float x){
    float w = -log1pf(-x * x), p;
    if (w < 5.f){
        w -= 2.5f;
        p = 2.81022636e-08f;
        p = fmaf(p, w, 3.43273939e-07f);
        p = fmaf(p, w, -3.5233877e-06f);
        p = fmaf(p, w, -4.39150654e-06f);
        p = fmaf(p, w, 0.00021858087f);
        p = fmaf(p, w, -0.00125372503f);
        p = fmaf(p, w, -0.00417768164f);
        p = fmaf(p, w, 0.246640727f);
        p = fmaf(p, w, 1.50140941f);
    } else {
        w = sqrtf(w) - 3.f;
        p = -0.000200214257f;
        p = fmaf(p, w, 0.000100950558f);
        p = fmaf(p, w, 0.00134934322f);
        p = fmaf(p, w, -0.00367342844f);
        p = fmaf(p, w, 0.00573950773f);
        p = fmaf(p, w, -0.0076224613f);
        p = fmaf(p, w, 0.00943887047f);
        p = fmaf(p, w, 1.00167406f);
        p = fmaf(p, w, 2.83297682f);
    }
    return p * x;
}

// ---------- A-warp matvec: pr, pz ----------
__device__ __forceinline__ void mvA(const float* xc, const float* hc, const float* w1a,
                                    u64 pr[4], u64 pz[4]){
#pragma unroll
    for (int k = 0; k < 4; k++){ pr[k] = pz[k] = 0ull; }
#pragma unroll 8
    for (int d = 0; d < 64; d++){
        float4 wa = *(const float4*)(w1a + d * 256);
        u64 WIR = dupf(wa.x), WHR = dupf(wa.y);
        u64 WIZ = dupf(wa.z), WHZ = dupf(wa.w);
        double2 XA = *(const double2*)(xc + d * 20);
        double2 XB = *(const double2*)(xc + d * 20 + 4);
        double2 HA = *(const double2*)(hc + d * 20);
        double2 HB = *(const double2*)(hc + d * 20 + 4);
        u64 x[4] = { d2u(XA.x), d2u(XA.y), d2u(XB.x), d2u(XB.y) };
        u64 h[4] = { d2u(HA.x), d2u(HA.y), d2u(HB.x), d2u(HB.y) };
#pragma unroll
        for (int k = 0; k < 4; k++){
            pr[k] = ff2(x[k], WIR, ff2(h[k], WHR, pr[k]));
            pz[k] = ff2(x[k], WIZ, ff2(h[k], WHZ, pz[k]));
        }
    }
}

// ---------- B-warp matvec: pin, phn, ar, az, an(next step) ----------
__device__ __forceinline__ void mvB(const float* xc, const float* hc,
                                    const float* w1b, const float* w0,
                                    u64 pin[4], u64 phn[4],
                                    u64 ar[4], u64 az[4], u64 an[4]){
#pragma unroll
    for (int k = 0; k < 4; k++){ pin[k]=phn[k]=ar[k]=az[k]=an[k]=0ull; }
#pragma unroll 4
    for (int d = 0; d < 64; d++){
        float2 wb = *(const float2*)(w1b + d * 128);
        float4 w0v = *(const float4*)(w0 + d * 256);
        u64 WIN = dupf(wb.x), WHN = dupf(wb.y);
        u64 W0R = dupf(w0v.x), W0Z = dupf(w0v.y), W0N = dupf(w0v.z);
        double2 XA = *(const double2*)(xc + d * 20);
        double2 XB = *(const double2*)(xc + d * 20 + 4);
        double2 HA = *(const double2*)(hc + d * 20);
        double2 HB = *(const double2*)(hc + d * 20 + 4);
        u64 x[4] = { d2u(XA.x), d2u(XA.y), d2u(XB.x), d2u(XB.y) };
        u64 h[4] = { d2u(HA.x), d2u(HA.y), d2u(HB.x), d2u(HB.y) };
#pragma unroll
        for (int k = 0; k < 4; k++){
            pin[k] = ff2(x[k], WIN, pin[k]);
            phn[k] = ff2(h[k], WHN, phn[k]);
            ar[k]  = ff2(x[k], W0R, ar[k]);
            az[k]  = ff2(x[k], W0Z, az[k]);
            an[k]  = ff2(x[k], W0N, an[k]);
        }
    }
}

// ---------- plain l0 matvec (decoder prologue, B-warp) ----------
__device__ __forceinline__ void l0mv(const float* h0c, const float* w0,
                                     u64* ar, u64* az, u64* an){
#pragma unroll
    for (int k = 0; k < 4; k++){ ar[k] = az[k] = an[k] = 0ull; }
#pragma unroll 4
    for (int d = 0; d < 64; d++){
        float4 w = *(const float4*)(w0 + d * 256);
        u64 WR = dupf(w.x), WZ = dupf(w.y), WN = dupf(w.z);
        double2 A = *(const double2*)(h0c + d * 20);
        double2 B = *(const double2*)(h0c + d * 20 + 4);
        u64 h[4] = { d2u(A.x), d2u(A.y), d2u(B.x), d2u(B.y) };
#pragma unroll
        for (int k = 0; k < 4; k++){
            ar[k] = ff2(h[k], WR, ar[k]);
            az[k] = ff2(h[k], WZ, az[k]);
            an[k] = ff2(h[k], WN, an[k]);
        }
    }
}

// L0 epilogue (A-warp): tk[8] = tokens for rows 8rg..8rg+7; writes h0 pairs
__device__ __forceinline__ void l0epi(const float* sm, float* h0n, int ug,
                                      const int* tk, const u64* ar, const u64* az,
                                      const u64* an, float b0r, float b0z, float b0n,
                                      float* hp0x, float* hp0y){
#pragma unroll
    for (int k = 0; k < 4; k++){
        const float* tb0 = sm + O_TAB + tk[2*k] * 192 + ug;
        const float* tb1 = sm + O_TAB + tk[2*k+1] * 192 + ug;
        float arx, ary, azx, azy, anx, any;
        upk2(ar[k], arx, ary); upk2(az[k], azx, azy); upk2(an[k], anx, any);
        float rx = sigf(tb0[0] + arx + b0r);
        float ry = sigf(tb1[0] + ary + b0r);
        float zx = sigf(tb0[64] + azx + b0z);
        float zy = sigf(tb1[64] + azy + b0z);
        float nx = tanhf(tb0[128] + rx * (anx + b0n));
        float ny = tanhf(tb1[128] + ry * (any + b0n));
        float hx = (1.f - zx) * nx + zx * hp0x[k];
        float hy = (1.f - zy) * ny + zy * hp0y[k];
        hp0x[k] = hx; hp0y[k] = hy;
        *(float2*)(h0n + 2 * k) = make_float2(hx, hy);
    }
}

// L1 epilogue (B-warp)
__device__ __forceinline__ void l1epi(float* h1n, const u64* pr, const u64* pz,
                                      const u64* pin, const u64* phn,
                                      float bi1r, float bi1z, float bi1n,
                                      float bh1r, float bh1z, float bh1n,
                                      float* hp1x, float* hp1y){
#pragma unroll
    for (int k = 0; k < 4; k++){
        float prx, pry, pzx, pzy, pix, piy, phx, phy;
        upk2(pr[k], prx, pry); upk2(pz[k], pzx, pzy);
        upk2(pin[k], pix, piy); upk2(phn[k], phx, phy);
        float rx = sigf(prx + bi1r + bh1r);
        float ry = sigf(pry + bi1r + bh1r);
        float zx = sigf(pzx + bi1z + bh1z);
        float zy = sigf(pzy + bi1z + bh1z);
        float nx = tanhf(pix + bi1n + rx * (phx + bh1n));
        float ny = tanhf(piy + bi1n + ry * (phy + bh1n));
        float hx = (1.f - zx) * nx + zx * hp1x[k];
        float hy = (1.f - zy) * ny + zy * hp1y[k];
        hp1x[k] = hx; hp1y[k] = hy;
        *(float2*)(h1n + 2 * k) = make_float2(hx, hy);
    }
}

// ---------- weight staging ----------
__device__ __forceinline__ void stage_weights(float* sm, int tid,
    const float* Whh0, const float* Wih1, const float* Whh1,
    const float* bhh0, const float* bih1, const float* bhh1){
    for (int i = tid; i < 4096; i += NT){
        int u = i >> 6, d = i & 63;
        int o = (d * 64 + u);
        sm[O_W1A + o*4 + 0] = Wih1[u*64 + d];
        sm[O_W1A + o*4 + 1] = Whh1[u*64 + d];
        sm[O_W1A + o*4 + 2] = Wih1[(64+u)*64 + d];
        sm[O_W1A + o*4 + 3] = Whh1[(64+u)*64 + d];
        sm[O_W1B + o*2 + 0] = Wih1[(128+u)*64 + d];
        sm[O_W1B + o*2 + 1] = Whh1[(128+u)*64 + d];
        sm[O_W0A + o*4 + 0] = Whh0[u*64 + d];
        sm[O_W0A + o*4 + 1] = Whh0[(64+u)*64 + d];
        sm[O_W0A + o*4 + 2] = Whh0[(128+u)*64 + d];
        sm[O_W0A + o*4 + 3] = 0.f;
    }
    for (int i = tid; i < 192; i += NT){
        sm[O_B0 + i] = bhh0[i];
        sm[O_BI1 + i] = bih1[i];
        sm[O_BH1 + i] = bhh1[i];
    }
}

// =========================== ENCODER ===========================
__global__ void __launch_bounds__(NT, 1) enc_k(
    const int* __restrict__ tokens, const float* __restrict__ emb,
    const float* __restrict__ Wih0, const float* __restrict__ Whh0,
    const float* __restrict__ bih0, const float* __restrict__ bhh0,
    const float* __restrict__ Wih1, const float* __restrict__ Whh1,
    const float* __restrict__ bih1, const float* __restrict__ bhh1,
    const float* __restrict__ muW, const float* __restrict__ mub,
    const float* __restrict__ varW, const float* __restrict__ varb,
    const float* __restrict__ prjW, const float* __restrict__ prjb,
    float* __restrict__ out, int wr_extra)
{
    extern __shared__ float sm[];
    int tid = threadIdx.x;
    stage_weights(sm, tid, Whh0, Wih1, Whh1, bhh0, bih1, bhh1);
    for (int i = tid; i < NTOK * 192; i += NT){
        int t = i / 192, u = i % 192;
        float s = bih0[u];
#pragma unroll
        for (int e = 0; e < 8; e++) s = fmaf(emb[t * 8 + e], Wih0[u * 8 + e], s);
        sm[O_TAB + i] = s;
    }
    for (int i = tid; i < 192; i += NT){
        sm[O_MUW + i] = muW[i]; sm[O_VARW + i] = varW[i]; sm[O_PRJW + i] = prjW[i];
    }
    if (tid < 3){ sm[O_MUB + tid] = mub[tid]; sm[O_VARB + tid] = varb[tid]; }
    for (int i = tid; i < 64; i += NT) sm[O_PRJB + i] = prjb[i];
    int base = blockIdx.x * 16;
    unsigned char* toksS = (unsigned char*)(sm + O_TOKS);
    for (int i = tid; i < 16 * 256; i += NT) toksS[i] = (unsigned char)tokens[base * 256 + i];
    for (int i = tid; i < 1280; i += NT){
        sm[O_H0B + i] = 0.f; sm[O_H0B + 1280 + i] = 0.f;
        sm[O_H1B + i] = 0.f; sm[O_H1B + 1280 + i] = 0.f;
    }
    __syncthreads();

    int warp = tid >> 5, lane = tid & 31;
    int wtype = warp >> 2;          // 0 = A, 1 = B
    int wg = warp & 3;
    int ul = lane & 15, rg = lane >> 4;
    int ug = wg * 16 + ul;
    int col = wg * 32 + lane;
    u64* XPR = (u64*)(sm + O_XPR);
    u64* XL0 = (u64*)(sm + O_XL0);

    if (wtype == 0){
        // ===== A-warp =====
        const float* w1a = sm + O_W1A + ug * 4;
        float b0r = sm[O_B0 + ug], b0z = sm[O_B0 + 64 + ug], b0n = sm[O_B0 + 128 + ug];
        float hp0x[4], hp0y[4];
#pragma unroll
        for (int k = 0; k < 4; k++){ hp0x[k] = hp0y[k] = 0.f; }
        u64 arC[4] = {0,0,0,0}, azC[4] = {0,0,0,0}, anC[4] = {0,0,0,0};

        for (int s = 0; s < 256; s++){
            int cb = s & 1, nb = cb ^ 1;
            int tk[8];
#pragma unroll
            for (int r = 0; r < 8; r++) tk[r] = toksS[(8 * rg + r) * 256 + s];
            l0epi(sm, sm + O_H0B + nb * 1280 + ug * 20 + 8 * rg, ug, tk,
                  arC, azC, anC, b0r, b0z, b0n, hp0x, hp0y);
            __syncthreads();   // SYNC1
            u64 pr[4], pz[4];
            mvA(sm + O_H0B + nb * 1280 + rg * 8, sm + O_H1B + cb * 1280 + rg * 8,
                w1a, pr, pz);
#pragma unroll
            for (int k = 0; k < 4; k++){
                XPR[(2*k    ) * 128 + col] = pr[k];
                XPR[(2*k + 1) * 128 + col] = pz[k];
            }
            __syncthreads();   // SYNC2
#pragma unroll
            for (int k = 0; k < 4; k++){
                arC[k] = XL0[(3*k    ) * 128 + col];
                azC[k] = XL0[(3*k + 1) * 128 + col];
                anC[k] = XL0[(3*k + 2) * 128 + col];
            }
        }
    } else {
        // ===== B-warp =====
        const float* w1b = sm + O_W1B + ug * 2;
        const float* w0  = sm + O_W0A + ug * 4;
        float i1r = sm[O_BI1 + ug], i1z = sm[O_BI1 + 64 + ug], i1n = sm[O_BI1 + 128 + ug];
        float h1r = sm[O_BH1 + ug], h1z = sm[O_BH1 + 64 + ug], h1n = sm[O_BH1 + 128 + ug];
        float hp1x[4], hp1y[4];
#pragma unroll
        for (int k = 0; k < 4; k++){ hp1x[k] = hp1y[k] = 0.f; }

        for (int s = 0; s < 256; s++){
            int cb = s & 1, nb = cb ^ 1;
            __syncthreads();   // SYNC1
            u64 pin[4], phn[4], ar[4], az[4], an[4];
            mvB(sm + O_H0B + nb * 1280 + rg * 8, sm + O_H1B + cb * 1280 + rg * 8,
                w1b, w0, pin, phn, ar, az, an);
#pragma unroll
            for (int k = 0; k < 4; k++){
                XL0[(3*k    ) * 128 + col] = ar[k];
                XL0[(3*k + 1) * 128 + col] = az[k];
                XL0[(3*k + 2) * 128 + col] = an[k];
            }
            __syncthreads();   // SYNC2
            u64 pr[4], pz[4];
#pragma unroll
            for (int k = 0; k < 4; k++){
                pr[k] = XPR[(2*k    ) * 128 + col];
                pz[k] = XPR[(2*k + 1) * 128 + col];
            }
            l1epi(sm + O_H1B + nb * 1280 + ug * 20 + 8 * rg, pr, pz, pin, phn,
                  i1r, i1z, i1n, h1r, h1z, h1n, hp1x, hp1y);
        }
    }
    __syncthreads();

    // final h1 in h1 buffer 0
    if (warp < 4 && lane < 12){
        int r = lane / 3, j = lane % 3;
        int lr = wg * 4 + r;
        int row = base + lr;
        float m = sm[O_MUB + j], v = sm[O_VARB + j];
        for (int d = 0; d < 64; d++){
            float h = sm[O_H1B + d * 20 + lr];
            m = fmaf(h, sm[O_MUW + j * 64 + d], m);
            v = fmaf(h, sm[O_VARW + j * 64 + d], v);
        }
        u32 bits = tf_bits32(0u, 1u, (u32)(row * 3 + j));
        float f01 = bits2f(bits);
        const float LO = -0.99999994f;
        float u = fmaxf(LO, fmaf(f01, 2.0f, LO));
        float eps = 1.41421356f * erfinv_f(u);
        float z = fmaf(eps, expf(0.5f * v), m);
        sm[O_ZS + lr * 3 + j] = z;
        if (wr_extra){ out[MUOFF + row * 3 + j] = m; out[LVOFF + row * 3 + j] = v; }
    }
    __syncthreads();
    for (int i = tid; i < 1024; i += NT){
        int r = i >> 6, d = i & 63;
        float z0 = sm[O_ZS + r * 3];
        float z1 = sm[O_ZS + r * 3 + 1];
        float z2 = sm[O_ZS + r * 3 + 2];
        float hx = sm[O_PRJB + d] + z0 * sm[O_PRJW + d * 3] + z1 * sm[O_PRJW + d * 3 + 1]
                 + z2 * sm[O_PRJW + d * 3 + 2];
        g_hz[(base + r) * 64 + d] = hx;
    }
}

// =========================== DECODER ===========================
__global__ void __launch_bounds__(NT, 1) dec_k(
    const float* __restrict__ dec_emb,
    const float* __restrict__ Wih0, const float* __restrict__ Whh0,
    const float* __restrict__ bih0, const float* __restrict__ bhh0,
    const float* __restrict__ Wih1, const float* __restrict__ Whh1,
    const float* __restrict__ bih1, const float* __restrict__ bhh1,
    const float* __restrict__ headW, const float* __restrict__ headb,
    float* __restrict__ out)
{
    extern __shared__ float sm[];
    int tid = threadIdx.x;
    stage_weights(sm, tid, Whh0, Wih1, Whh1, bhh0, bih1, bhh1);
    for (int i = tid; i < NTOK * 192; i += NT){
        int t = i / 192, u = i % 192;
        float s = bih0[u];
        for (int d = 0; d < 64; d++) s = fmaf(dec_emb[t * 64 + d], Wih0[u * 64 + d], s);
        sm[O_TAB + i] = s;
    }
    for (int i = tid; i < 256; i += NT) sm[O_HW + i] = headW[i];
    if (tid < 4) sm[O_HB2 + tid] = headb[tid];
    u32* K0 = (u32*)(sm + O_K0);
    u32* K1 = (u32*)(sm + O_K1);
    for (int i = tid; i < 256; i += NT){
        u32 a, b; threefry(0u, 2u, 0u, (u32)i, a, b);
        K0[i] = a; K1[i] = b;
    }
    int* tokD = (int*)(sm + O_TOKD);
    if (tid < 16) tokD[tid] = STARTTOK;
    int base = blockIdx.x * 16;
    for (int i = tid; i < 1024; i += NT){
        int r = i >> 6, d = i & 63;
        float v = g_hz[(base + r) * 64 + d];
        sm[O_H0B + d * 20 + r] = v;
        sm[O_H1B + d * 20 + r] = v;
    }
    __syncthreads();

    int warp = tid >> 5, lane = tid & 31;
    int wtype = warp >> 2;
    int wg = warp & 3;
    int ul = lane & 15, rg = lane >> 4;
    int ug = wg * 16 + ul;
    int col = wg * 32 + lane;
    u64* XPR = (u64*)(sm + O_XPR);
    u64* XL0 = (u64*)(sm + O_XL0);
    const float TINYF = 1.17549435e-38f;

    if (wtype == 0){
        // ===== A-warp =====
        const float* w1a = sm + O_W1A + ug * 4;
        float b0r = sm[O_B0 + ug], b0z = sm[O_B0 + 64 + ug], b0n = sm[O_B0 + 128 + ug];
        float hp0x[4], hp0y[4];
#pragma unroll
        for (int k = 0; k < 4; k++){
            float2 h = *(const float2*)(sm + O_H0B + ug * 20 + 8 * rg + 2 * k);
            hp0x[k] = h.x; hp0y[k] = h.y;
        }
        __syncthreads();   // PRO_SYNC: wait for B's prologue l0mv partials
        u64 arC[4], azC[4], anC[4];
#pragma unroll
        for (int k = 0; k < 4; k++){
            arC[k] = XL0[(3*k    ) * 128 + col];
            azC[k] = XL0[(3*k + 1) * 128 + col];
            anC[k] = XL0[(3*k + 2) * 128 + col];
        }
        for (int s = 0; s < 256; s++){
            int cb = s & 1, nb = cb ^ 1;
            int tk[8];
#pragma unroll
            for (int r = 0; r < 8; r++) tk[r] = tokD[8 * rg + r];
            l0epi(sm, sm + O_H0B + nb * 1280 + ug * 20 + 8 * rg, ug, tk,
                  arC, azC, anC, b0r, b0z, b0n, hp0x, hp0y);
            __syncthreads();   // SYNC1
            u64 pr[4], pz[4];
            mvA(sm + O_H0B + nb * 1280 + rg * 8, sm + O_H1B + cb * 1280 + rg * 8,
                w1a, pr, pz);
#pragma unroll
            for (int k = 0; k < 4; k++){
                XPR[(2*k    ) * 128 + col] = pr[k];
                XPR[(2*k + 1) * 128 + col] = pz[k];
            }
            __syncthreads();   // SYNC2
#pragma unroll
            for (int k = 0; k < 4; k++){
                arC[k] = XL0[(3*k    ) * 128 + col];
                azC[k] = XL0[(3*k + 1) * 128 + col];
                anC[k] = XL0[(3*k + 2) * 128 + col];
            }
            __syncthreads();   // SYNC3: tokD + h1[nb] published by B
        }
    } else {
        // ===== B-warp =====
        const float* w1b = sm + O_W1B + ug * 2;
        const float* w0  = sm + O_W0A + ug * 4;
        float i1r = sm[O_BI1 + ug], i1z = sm[O_BI1 + 64 + ug], i1n = sm[O_BI1 + 128 + ug];
        float h1r = sm[O_BH1 + ug], h1z = sm[O_BH1 + 64 + ug], h1n = sm[O_BH1 + 128 + ug];
        u64 WV[4];
#pragma unroll
        for (int v = 0; v < 4; v++) WV[v] = dupf(sm[O_HW + v * 64 + ug]);
        float hp1x[4], hp1y[4];
#pragma unroll
        for (int k = 0; k < 4; k++){
            float2 h = *(const float2*)(sm + O_H1B + ug * 20 + 8 * rg + 2 * k);
            hp1x[k] = h.x; hp1y[k] = h.y;
        }
        // prologue: l0 matvec for step 0 on h0 = hz (buffer 0)
        {
            u64 ar[4], az[4], an[4];
            l0mv(sm + O_H0B + rg * 8, w0, ar, az, an);
#pragma unroll
            for (int k = 0; k < 4; k++){
                XL0[(3*k    ) * 128 + col] = ar[k];
                XL0[(3*k + 1) * 128 + col] = az[k];
                XL0[(3*k + 2) * 128 + col] = an[k];
            }
        }
        __syncthreads();   // PRO_SYNC

        for (int s = 0; s < 256; s++){
            int cb = s & 1, nb = cb ^ 1;
            __syncthreads();   // SYNC1
            u64 pin[4], phn[4], ar[4], az[4], an[4];
            mvB(sm + O_H0B + nb * 1280 + rg * 8, sm + O_H1B + cb * 1280 + rg * 8,
                w1b, w0, pin, phn, ar, az, an);
#pragma unroll
            for (int k = 0; k < 4; k++){
                XL0[(3*k    ) * 128 + col] = ar[k];
                XL0[(3*k + 1) * 128 + col] = az[k];
                XL0[(3*k + 2) * 128 + col] = an[k];
            }
            __syncthreads();   // SYNC2
            u64 pr[4], pz[4];
#pragma unroll
            for (int k = 0; k < 4; k++){
                pr[k] = XPR[(2*k    ) * 128 + col];
                pz[k] = XPR[(2*k + 1) * 128 + col];
            }
            l1epi(sm + O_H1B + nb * 1280 + ug * 20 + 8 * rg, pr, pz, pin, phn,
                  i1r, i1z, i1n, h1r, h1z, h1n, hp1x, hp1y);

            // head partials per (pair, v), reduce over this warp's 16 units
            u64 pp[16];
#pragma unroll
            for (int k = 0; k < 4; k++){
                u64 hp = pack2(hp1x[k], hp1y[k]);
#pragma unroll
                for (int v = 0; v < 4; v++) pp[k * 4 + v] = ff2(hp, WV[v], 0ull);
            }
#pragma unroll
            for (int m = 1; m < 16; m <<= 1){
#pragma unroll
                for (int j = 0; j < 16; j++){
                    double o = __shfl_xor_sync(0xffffffffu,
                                               __longlong_as_double((long long)pp[j]), m);
                    pp[j] = add2(pp[j], d2u(o));
                }
            }
            if (ul == 0){
#pragma unroll
                for (int k = 0; k < 4; k++)
#pragma unroll
                    for (int v = 0; v < 4; v++){
                        float a, b; upk2(pp[k * 4 + v], a, b);
                        *(float2*)(sm + O_LSTG + (wg * 4 + v) * 16 + 8 * rg + 2 * k)
                            = make_float2(a, b);
                    }
            }
            asm volatile("bar.sync 1, 128;" ::: "memory");   // B-warps only

            // sample: B-warp wg handles rows wg*4..wg*4+3
            {
                int k = lane & 15, r = k >> 2, v = k & 3;
                int lr = wg * 4 + r;
                int row = base + lr;
                float sum = ((sm[O_LSTG + v * 16 + lr] + sm[O_LSTG + (4 + v) * 16 + lr])
                             + sm[O_LSTG + (8 + v) * 16 + lr]) + sm[O_LSTG + (12 + v) * 16 + lr];
                float logit = sum + sm[O_HB2 + v];
                u32 bits = tf_bits32(K0[s], K1[s], (u32)(row * 4 + v));
                float f01 = bits2f(bits);
                float u = fmaxf(TINYF, f01 + TINYF);
                float g = -logf(-logf(u));
                float y = logit + g;
                float mx = logit;
                mx = fmaxf(mx, __shfl_xor_sync(0xffffffffu, mx, 1));
                mx = fmaxf(mx, __shfl_xor_sync(0xffffffffu, mx, 2));
                float e = expf(logit - mx);
                float den = e;
                den += __shfl_xor_sync(0xffffffffu, den, 1);
                den += __shfl_xor_sync(0xffffffffu, den, 2);
                if (lane < 16) out[((size_t)row * 256 + s) * 4 + v] = e / den;
                float by = y; int bi = v;
                { float oy = __shfl_xor_sync(0xffffffffu, by, 1);
                  int   oi = __shfl_xor_sync(0xffffffffu, bi, 1);
                  if (oy > by || (oy == by && oi < bi)){ by = oy; bi = oi; } }
                { float oy = __shfl_xor_sync(0xffffffffu, by, 2);
                  int   oi = __shfl_xor_sync(0xffffffffu, bi, 2);
                  if (oy > by || (oy == by && oi < bi)){ by = oy; bi = oi; } }
                if (lane < 16 && v == 0) tokD[lr] = bi;
            }
            __syncthreads();   // SYNC3
        }
    }
}

__global__ void tok_cast_k(const int* __restrict__ tokens, float* __restrict__ dst){
    int i = blockIdx.x * blockDim.x + threadIdx.x;
    if (i < BBATCH * SSEQ) dst[i] = (float)tokens[i];
}

extern "C" void kernel_launch(void* const* d_in, const int* in_sizes, int n_in,
                              void* d_out, int out_size){
    const int*   tokens = (const int*)  d_in[0];
    const float* emb    = (const float*)d_in[1];
    const float* eWih0  = (const float*)d_in[2];
    const float* eWhh0  = (const float*)d_in[3];
    const float* ebih0  = (const float*)d_in[4];
    const float* ebhh0  = (const float*)d_in[5];
    const float* eWih1  = (const float*)d_in[6];
    const float* eWhh1  = (const float*)d_in[7];
    const float* ebih1  = (const float*)d_in[8];
    const float* ebhh1  = (const float*)d_in[9];
    const float* muW    = (const float*)d_in[10];
    const float* mub    = (const float*)d_in[11];
    const float* varW   = (const float*)d_in[12];
    const float* varb   = (const float*)d_in[13];
    const float* demb   = (const float*)d_in[14];
    const float* prjW   = (const float*)d_in[15];
    const float* prjb   = (const float*)d_in[16];
    const float* dWih0  = (const float*)d_in[17];
    const float* dWhh0  = (const float*)d_in[18];
    const float* dbih0  = (const float*)d_in[19];
    const float* dbhh0  = (const float*)d_in[20];
    const float* dWih1  = (const float*)d_in[21];
    const float* dWhh1  = (const float*)d_in[22];
    const float* dbih1  = (const float*)d_in[23];
    const float* dbhh1  = (const float*)d_in[24];
    const float* headW  = (const float*)d_in[25];
    const float* headb  = (const float*)d_in[26];
    float* out = (float*)d_out;
    int full = (out_size >= FULLN) ? 1 : 0;

    cudaFuncSetAttribute(enc_k, cudaFuncAttributeMaxDynamicSharedMemorySize, ENC_F * 4);
    cudaFuncSetAttribute(dec_k, cudaFuncAttributeMaxDynamicSharedMemorySize, DEC_F * 4);

    enc_k<<<128, NT, ENC_F * 4>>>(tokens, emb, eWih0, eWhh0, ebih0, ebhh0,
                                  eWih1, eWhh1, ebih1, ebhh1,
                                  muW, mub, varW, varb, prjW, prjb, out, full);
    dec_k<<<128, NT, DEC_F * 4>>>(demb, dWih0, dWhh0, dbih0, dbhh0,
                                  dWih1, dWhh1, dbih1, dbhh1, headW, headb, out);
    if (full)
        tok_cast_k<<<(BBATCH * SSEQ + 255) / 256, 256>>>(tokens, out + TOKOFF);
}